// round 5
// baseline (speedup 1.0000x reference)
#include <cuda_runtime.h>
#include <cuda_fp16.h>
#include <cuda_bf16.h>
#include <cstdint>

#define NN   100000
#define NE   600000
#define DD   128
#define NG   200
#define NLAY 5
#define NOUT 10
#define NBLK 98                 // ceil(NN/1024)
#define FILL_BLKS 1172          // ceil(NE/512)
#define EPI_BLKS  391           // ceil(NN/256)
#define BETAF 0.0077821404f     // ln(1 + 1/128)
#define OMBF  0.9922178596f     // 1 - BETA

// ---------------- scratch (device globals; no allocations) ----------------
// All accumulator-style globals start zero (static init) and are re-zeroed by
// cleanup_kernel at the END of every launch, so each graph replay starts clean.
__device__ __align__(16) __half d_hsh[NN*DD];  // fp16: h * norm_out (gather table)
__device__ __align__(16) float  d_rst[NN*DD];
__device__ float d_norm_out[NN];
__device__ float d_sdeg[NN];
__device__ float d_norm_in [NN];
__device__ int   d_deg_out[NN];
__device__ int   d_deg_in [NN];
__device__ int   d_rowptr[NN+1];
__device__ int   d_cursor[NN];
__device__ int   d_col[NE];
__device__ float d_pooled[(NLAY+1)*NG*DD];
__device__ float d_bnsum[NLAY*2*DD];
__device__ int   d_pub[NBLK];                  // decoupled-lookback publish words

// ---------------- degree histogram ----------------
__global__ void deg_kernel(const int* __restrict__ src, const int* __restrict__ dst) {
    int i = blockIdx.x * blockDim.x + threadIdx.x;
    if (i < NE) {
        atomicAdd(&d_deg_out[src[i]], 1);
        atomicAdd(&d_deg_in [dst[i]], 1);
    }
}

// ---------------- fused norms + single-pass exclusive scan (lookback) -------
__global__ __launch_bounds__(256) void scan_fused() {
    __shared__ int sh[256];
    __shared__ int spre[128];
    int t = threadIdx.x, b = blockIdx.x, base = b * 1024;

    int loc[4]; int s = 0;
    #pragma unroll
    for (int i = 0; i < 4; i++) {
        int idx = base + t * 4 + i;
        int v = 0;
        if (idx < NN) {
            int dgo = max(d_deg_out[idx], 1);
            d_norm_out[idx] = rsqrtf((float)dgo);
            d_sdeg[idx]     = sqrtf((float)dgo);
            v = d_deg_in[idx];
            d_norm_in[idx]  = rsqrtf((float)max(v, 1));
        }
        loc[i] = s; s += v;
    }
    sh[t] = s; __syncthreads();
    for (int off = 1; off < 256; off <<= 1) {
        int v = (t >= off) ? sh[t - off] : 0;
        __syncthreads();
        sh[t] += v;
        __syncthreads();
    }
    // publish this block's aggregate (value+1; 0 == not ready)
    if (t == 0) atomicExch(&d_pub[b], sh[255] + 1);

    // lookback: lane t spins on predecessor t (all 98 blocks co-resident)
    int myagg = 0;
    if (t < b) {
        volatile int* p = &d_pub[t];
        int v;
        do { v = *p; } while (v == 0);
        myagg = v - 1;
    }
    if (t < 128) spre[t] = myagg;
    __syncthreads();
    for (int off = 64; off > 0; off >>= 1) {
        if (t < off) spre[t] += spre[t + off];
        __syncthreads();
    }
    int bpre = spre[0];

    int tpre = (t == 0) ? 0 : sh[t - 1];
    #pragma unroll
    for (int i = 0; i < 4; i++) {
        int idx = base + t * 4 + i;
        if (idx < NN) { int p = bpre + tpre + loc[i]; d_rowptr[idx] = p; d_cursor[idx] = p; }
    }
    if (b == 0 && t == 0) d_rowptr[NN] = NE;
}

// ---------------- BN+ReLU epilogue body ----------------
template <bool INIT>
__device__ __forceinline__ void epilogue_body(const float* __restrict__ src,
                                              const int* __restrict__ gid,
                                              int pslot,
                                              const float* __restrict__ bng,
                                              const float* __restrict__ bnb,
                                              const float* __restrict__ bnslot,
                                              int blk) {
    __shared__ float spool[16][128];
    int t = threadIdx.x;
    int base = blk * 256;
    int nodes = min(256, NN - base);
    if (nodes <= 0) return;
    int g0 = gid[base];
    int span = gid[base + nodes - 1] - g0 + 1;
    bool fits = (span <= 16);
    if (fits) for (int i = t; i < span * 128; i += 512) ((float*)spool)[i] = 0.f;
    __syncthreads();

    int d = t & 127;
    int q = t >> 7;   // 0..3
    float bg = 0.f, bb = 0.f, mu = 0.f, is = 0.f;
    if (!INIT) {
        bg = bng[d]; bb = bnb[d];
        float s = bnslot[d], sq = bnslot[128 + d];
        mu = s * (1.0f / NN);
        is = rsqrtf(sq * (1.0f / NN) - mu * mu + 1e-5f);
    }
    const float* sp = INIT ? src : d_rst;

    float racc = 0.f; int rlg = -1;
    for (int i = q; i < nodes; i += 4) {
        int n = base + i;
        float v = sp[n * 128 + d];
        float y;
        if (INIT) y = v;
        else      y = fmaxf((v - mu) * is * bg + bb, 0.0f);
        d_hsh[n * 128 + d] = __float2half_rn(y * d_norm_out[n]);
        int lg = gid[n] - g0;
        if (fits) {
            if (lg != rlg) {
                if (rlg >= 0) atomicAdd(&spool[rlg][d], racc);
                rlg = lg; racc = 0.f;
            }
            racc += y;
        } else {
            atomicAdd(&d_pooled[(pslot * NG + g0 + lg) * 128 + d], y);
        }
    }
    if (fits && rlg >= 0) atomicAdd(&spool[rlg][d], racc);
    __syncthreads();
    if (fits)
        for (int lg = q; lg < span; lg += 4)
            atomicAdd(&d_pooled[(pslot * NG + g0 + lg) * 128 + d], spool[lg][d]);
}

// fused: CSR fill (blocks [0,FILL_BLKS)) + init epilogue (blocks after)
__global__ __launch_bounds__(512) void fill_epi_kernel(const int* __restrict__ src,
                                                       const int* __restrict__ dst,
                                                       const float* __restrict__ feat,
                                                       const int* __restrict__ gid) {
    if (blockIdx.x < FILL_BLKS) {
        int i = blockIdx.x * 512 + threadIdx.x;
        if (i < NE) {
            int d = dst[i];
            int pos = atomicAdd(&d_cursor[d], 1);
            d_col[pos] = src[i];
        }
    } else {
        epilogue_body<true>(feat, gid, 0, nullptr, nullptr, nullptr,
                            blockIdx.x - FILL_BLKS);
    }
}

__global__ __launch_bounds__(512) void epilogue_kernel(const int* __restrict__ gid,
                                                       int pslot,
                                                       const float* __restrict__ bng,
                                                       const float* __restrict__ bnb,
                                                       const float* __restrict__ bnslot) {
    epilogue_body<false>(nullptr, gid, pslot, bng, bnb, bnslot, blockIdx.x);
}

// ---------------- SpMM: warp per dst node, lane-cooperative col fetch -------
__device__ __forceinline__ void acc_node(float4& acc, const __half* __restrict__ hs,
                                         int s, int lane) {
    uint2 u = *reinterpret_cast<const uint2*>(hs + s * 128 + lane * 4);
    float2 fa = __half22float2(*reinterpret_cast<__half2*>(&u.x));
    float2 fb = __half22float2(*reinterpret_cast<__half2*>(&u.y));
    acc.x += fa.x; acc.y += fa.y; acc.z += fb.x; acc.w += fb.y;
}

__global__ __launch_bounds__(256) void spmm_kernel() {
    int warp = (blockIdx.x * blockDim.x + threadIdx.x) >> 5;
    int lane = threadIdx.x & 31;
    if (warp >= NN) return;
    int beg = d_rowptr[warp], end = d_rowptr[warp + 1];
    float4 acc = make_float4(0.f, 0.f, 0.f, 0.f);
    const __half* hs = d_hsh;
    // One coalesced load fetches up to 32 edge indices; shfl broadcasts them.
    // All gathers for a chunk issue back-to-back (MLP = chunk size).
    for (int e0 = beg; e0 < end; e0 += 32) {
        int m = min(32, end - e0);
        int c = (lane < m) ? __ldg(&d_col[e0 + lane]) : 0;
        int j = 0;
        for (; j + 4 <= m; j += 4) {
            int s0 = __shfl_sync(0xffffffffu, c, j);
            int s1 = __shfl_sync(0xffffffffu, c, j + 1);
            int s2 = __shfl_sync(0xffffffffu, c, j + 2);
            int s3 = __shfl_sync(0xffffffffu, c, j + 3);
            acc_node(acc, hs, s0, lane);
            acc_node(acc, hs, s1, lane);
            acc_node(acc, hs, s2, lane);
            acc_node(acc, hs, s3, lane);
        }
        for (; j < m; j++) {
            int s = __shfl_sync(0xffffffffu, c, j);
            acc_node(acc, hs, s, lane);
        }
    }
    float ni = 0.9f * d_norm_in[warp];
    float rs = 0.1f * d_sdeg[warp];
    float4 hv = make_float4(0.f, 0.f, 0.f, 0.f);
    acc_node(hv, hs, warp, lane);     // residual = hs[self] * sdeg
    float4 r;
    r.x = ni * acc.x + rs * hv.x;
    r.y = ni * acc.y + rs * hv.y;
    r.z = ni * acc.z + rs * hv.z;
    r.w = ni * acc.w + rs * hv.w;
    reinterpret_cast<float4*>(d_rst)[warp * 32 + lane] = r;
}

// ---------------- GEMM: rst = (1-B)*rst + B*(rst@W) + bias, in place -------
__global__ __launch_bounds__(256) void gemm_kernel(const float* __restrict__ W,
                                                   const float* __restrict__ bias,
                                                   float* __restrict__ bnslot) {
    __shared__ __nv_bfloat16 As[128][72];
    __shared__ __nv_bfloat16 Ws[64][136];
    __shared__ float bns[2][128];
    int t = threadIdx.x, lane = t & 31, wid = t >> 5;
    int rowbase = blockIdx.x * 128;
    if (t < 128) { bns[0][t] = 0.f; bns[1][t] = 0.f; }
    float acc[16][4];
    #pragma unroll
    for (int i = 0; i < 16; i++) { acc[i][0]=0.f; acc[i][1]=0.f; acc[i][2]=0.f; acc[i][3]=0.f; }

    for (int kk = 0; kk < 128; kk += 64) {
        for (int i = t; i < 128 * 16; i += 256) {
            int r = i >> 4, c4 = i & 15;
            int grow = rowbase + r;
            float4 v = make_float4(0.f, 0.f, 0.f, 0.f);
            if (grow < NN)
                v = reinterpret_cast<const float4*>(d_rst)[grow * 32 + (kk >> 2) + c4];
            __nv_bfloat162* ap = reinterpret_cast<__nv_bfloat162*>(&As[r][c4 * 4]);
            ap[0] = __floats2bfloat162_rn(v.x, v.y);
            ap[1] = __floats2bfloat162_rn(v.z, v.w);
        }
        for (int i = t; i < 64 * 32; i += 256) {
            int r = i >> 5, c4 = i & 31;
            float4 v = reinterpret_cast<const float4*>(W)[(kk + r) * 32 + c4];
            __nv_bfloat162* wp = reinterpret_cast<__nv_bfloat162*>(&Ws[r][c4 * 4]);
            wp[0] = __floats2bfloat162_rn(v.x, v.y);
            wp[1] = __floats2bfloat162_rn(v.z, v.w);
        }
        __syncthreads();

        #pragma unroll
        for (int k0 = 0; k0 < 64; k0 += 16) {
            uint32_t a[4];
            unsigned aaddr = (unsigned)__cvta_generic_to_shared(
                &As[wid * 16 + (lane & 15)][k0 + ((lane >> 1) & 8)]);
            asm volatile("ldmatrix.sync.aligned.m8n8.x4.shared.b16 {%0,%1,%2,%3}, [%4];"
                         : "=r"(a[0]), "=r"(a[1]), "=r"(a[2]), "=r"(a[3]) : "r"(aaddr));
            unsigned bbase = (unsigned)__cvta_generic_to_shared(&Ws[k0 + (lane & 15)][0]);
            #pragma unroll
            for (int nb = 0; nb < 16; nb++) {
                uint32_t b[2];
                asm volatile("ldmatrix.sync.aligned.m8n8.x2.trans.shared.b16 {%0,%1}, [%2];"
                             : "=r"(b[0]), "=r"(b[1]) : "r"(bbase + nb * 16));
                asm volatile("mma.sync.aligned.m16n8k16.row.col.f32.bf16.bf16.f32 "
                             "{%0,%1,%2,%3},{%4,%5,%6,%7},{%8,%9},{%0,%1,%2,%3};"
                             : "+f"(acc[nb][0]), "+f"(acc[nb][1]), "+f"(acc[nb][2]), "+f"(acc[nb][3])
                             : "r"(a[0]), "r"(a[1]), "r"(a[2]), "r"(a[3]), "r"(b[0]), "r"(b[1]));
            }
        }
        __syncthreads();
    }
    int r0 = rowbase + wid * 16 + (lane >> 2);
    int r1 = r0 + 8;
    #pragma unroll
    for (int nb = 0; nb < 16; nb++) {
        int c = nb * 8 + (lane & 3) * 2;
        float b0 = bias[c], b1 = bias[c + 1];
        float s0 = 0.f, s1 = 0.f, q0 = 0.f, q1 = 0.f;
        if (r0 < NN) {
            float* p = &d_rst[r0 * 128 + c];
            float y0 = OMBF * p[0] + BETAF * acc[nb][0] + b0;
            float y1 = OMBF * p[1] + BETAF * acc[nb][1] + b1;
            p[0] = y0; p[1] = y1;
            s0 += y0; s1 += y1; q0 += y0 * y0; q1 += y1 * y1;
        }
        if (r1 < NN) {
            float* p = &d_rst[r1 * 128 + c];
            float y0 = OMBF * p[0] + BETAF * acc[nb][2] + b0;
            float y1 = OMBF * p[1] + BETAF * acc[nb][3] + b1;
            p[0] = y0; p[1] = y1;
            s0 += y0; s1 += y1; q0 += y0 * y0; q1 += y1 * y1;
        }
        atomicAdd(&bns[0][c], s0);
        atomicAdd(&bns[0][c + 1], s1);
        atomicAdd(&bns[1][c], q0);
        atomicAdd(&bns[1][c + 1], q1);
    }
    __syncthreads();
    if (t < 128) {
        atomicAdd(&bnslot[t], bns[0][t]);
        atomicAdd(&bnslot[128 + t], bns[1][t]);
    }
}

// ---------------- readout ----------------
__global__ void final_kernel(const float* __restrict__ lin_w,
                             const float* __restrict__ lin_b,
                             float* __restrict__ out) {
    __shared__ float sp[6][128];
    __shared__ float sc[NOUT];
    int g = blockIdx.x, t = threadIdx.x;   // 128 threads
    for (int i = t; i < 6 * 128; i += 128)
        sp[i / 128][i & 127] = d_pooled[((i / 128) * NG + g) * 128 + (i & 127)];
    __syncthreads();
    if (t < NOUT) {
        float s = 0.f;
        for (int i = 0; i < 6; i++) {
            s += lin_b[i * NOUT + t];
            const float* w = lin_w + i * 128 * NOUT;
            float ps = 0.f;
            for (int k = 0; k < 128; k++) ps += sp[i][k] * w[k * NOUT + t];
            s += ps;
        }
        sc[t] = s;
    }
    __syncthreads();
    if (t < NOUT) {
        float m = sc[0];
        #pragma unroll
        for (int i = 1; i < NOUT; i++) m = fmaxf(m, sc[i]);
        float lse = 0.f;
        #pragma unroll
        for (int i = 0; i < NOUT; i++) lse += expf(sc[i] - m);
        lse = logf(lse);
        out[g * NOUT + t] = sc[t] - m - lse;
    }
    float mp = sp[1][t] + sp[2][t] + sp[3][t] + sp[4][t] + sp[5][t];
    out[NG * NOUT + g * 128 + t] = mp * 0.2f;
}

// ---------------- trailing cleanup: restore zero state for next replay -----
__global__ void cleanup_kernel() {
    int i = blockIdx.x * blockDim.x + threadIdx.x;
    if (i < NN) { d_deg_out[i] = 0; d_deg_in[i] = 0; }
    if (i < (NLAY+1)*NG*DD) d_pooled[i] = 0.f;
    if (i < NLAY*2*DD) d_bnsum[i] = 0.f;
    if (i < NBLK) d_pub[i] = 0;
}

// ---------------- host launcher ----------------
extern "C" void kernel_launch(void* const* d_in, const int* in_sizes, int n_in,
                              void* d_out, int out_size) {
    const float* feat  = (const float*)d_in[0];
    const int*   src   = (const int*)  d_in[1];
    const int*   dst   = (const int*)  d_in[2];
    const int*   gid   = (const int*)  d_in[3];
    const float* gcn_w = (const float*)d_in[4];
    const float* gcn_b = (const float*)d_in[5];
    const float* bn_g  = (const float*)d_in[6];
    const float* bn_b  = (const float*)d_in[7];
    const float* lin_w = (const float*)d_in[8];
    const float* lin_b = (const float*)d_in[9];
    float* out = (float*)d_out;
    (void)in_sizes; (void)n_in; (void)out_size;

    float* bnsum_base;
    cudaGetSymbolAddress((void**)&bnsum_base, d_bnsum);

    deg_kernel<<<(NE + 255) / 256, 256>>>(src, dst);          // idx 0
    scan_fused<<<NBLK, 256>>>();                              // idx 1
    fill_epi_kernel<<<FILL_BLKS + EPI_BLKS, 512>>>(src, dst, feat, gid);  // idx 2

    for (int l = 0; l < NLAY; l++) {
        spmm_kernel<<<(NN * 32 + 255) / 256, 256>>>();        // first spmm = idx 3
        gemm_kernel<<<(NN + 127) / 128, 256>>>(gcn_w + l * DD * DD, gcn_b + l * DD,
                                               bnsum_base + l * 2 * DD);
        epilogue_kernel<<<EPI_BLKS, 512>>>(gid, l + 1,
                                           bn_g + l * DD, bn_b + l * DD,
                                           bnsum_base + l * 2 * DD);
    }
    final_kernel<<<NG, 128>>>(lin_w, lin_b, out);
    cleanup_kernel<<<600, 256>>>();
}

// round 6
// speedup vs baseline: 1.6881x; 1.6881x over previous
#include <cuda_runtime.h>
#include <cuda_fp16.h>
#include <cuda_bf16.h>
#include <cstdint>

#define NN   100000
#define NE   600000
#define DD   128
#define NG   200
#define NLAY 5
#define NOUT 10
#define NBLK 98                 // ceil(NN/1024)
#define FILL_BLKS 1172          // ceil(NE/512)
#define EPI_BLKS  391           // ceil(NN/256)
#define BETAF 0.0077821404f     // ln(1 + 1/128)
#define OMBF  0.9922178596f     // 1 - BETA

// ---------------- scratch (device globals; no allocations) ----------------
// All accumulator-style globals start zero (static init) and are re-zeroed by
// cleanup_kernel at the END of every launch, so each graph replay starts clean.
__device__ __align__(16) __half d_hsh[NN*DD];  // fp16: h * norm_out (gather table)
__device__ __align__(16) float  d_rst[NN*DD];
__device__ float d_norm_out[NN];
__device__ float d_sdeg[NN];
__device__ float d_norm_in [NN];
__device__ int   d_deg_out[NN];
__device__ int   d_deg_in [NN];
__device__ int   d_rowptr[NN+1];
__device__ int   d_cursor[NN];
__device__ int   d_col[NE];
__device__ float d_pooled[(NLAY+1)*NG*DD];
__device__ float d_bnsum[NLAY*2*DD];
__device__ int   d_pub[NBLK];                  // decoupled-lookback publish words

// ---------------- degree histogram ----------------
__global__ void deg_kernel(const int* __restrict__ src, const int* __restrict__ dst) {
    int i = blockIdx.x * blockDim.x + threadIdx.x;
    if (i < NE) {
        atomicAdd(&d_deg_out[src[i]], 1);
        atomicAdd(&d_deg_in [dst[i]], 1);
    }
}

// ---------------- fused norms + single-pass exclusive scan (lookback) -------
__global__ __launch_bounds__(256) void scan_fused() {
    __shared__ int sh[256];
    __shared__ int spre[128];
    int t = threadIdx.x, b = blockIdx.x, base = b * 1024;

    int loc[4]; int s = 0;
    #pragma unroll
    for (int i = 0; i < 4; i++) {
        int idx = base + t * 4 + i;
        int v = 0;
        if (idx < NN) {
            int dgo = max(d_deg_out[idx], 1);
            d_norm_out[idx] = rsqrtf((float)dgo);
            d_sdeg[idx]     = sqrtf((float)dgo);
            v = d_deg_in[idx];
            d_norm_in[idx]  = rsqrtf((float)max(v, 1));
        }
        loc[i] = s; s += v;
    }
    sh[t] = s; __syncthreads();
    for (int off = 1; off < 256; off <<= 1) {
        int v = (t >= off) ? sh[t - off] : 0;
        __syncthreads();
        sh[t] += v;
        __syncthreads();
    }
    // publish this block's aggregate (value+1; 0 == not ready)
    if (t == 0) atomicExch(&d_pub[b], sh[255] + 1);

    // lookback: lane t spins on predecessor t (all 98 blocks co-resident)
    int myagg = 0;
    if (t < b) {
        volatile int* p = &d_pub[t];
        int v;
        do { v = *p; } while (v == 0);
        myagg = v - 1;
    }
    if (t < 128) spre[t] = myagg;
    __syncthreads();
    for (int off = 64; off > 0; off >>= 1) {
        if (t < off) spre[t] += spre[t + off];
        __syncthreads();
    }
    int bpre = spre[0];

    int tpre = (t == 0) ? 0 : sh[t - 1];
    #pragma unroll
    for (int i = 0; i < 4; i++) {
        int idx = base + t * 4 + i;
        if (idx < NN) { int p = bpre + tpre + loc[i]; d_rowptr[idx] = p; d_cursor[idx] = p; }
    }
    if (b == 0 && t == 0) d_rowptr[NN] = NE;
}

// ---------------- BN+ReLU epilogue body ----------------
template <bool INIT>
__device__ __forceinline__ void epilogue_body(const float* __restrict__ src,
                                              const int* __restrict__ gid,
                                              int pslot,
                                              const float* __restrict__ bng,
                                              const float* __restrict__ bnb,
                                              const float* __restrict__ bnslot,
                                              int blk) {
    __shared__ float spool[16][128];
    int t = threadIdx.x;
    int base = blk * 256;
    int nodes = min(256, NN - base);
    if (nodes <= 0) return;
    int g0 = gid[base];
    int span = gid[base + nodes - 1] - g0 + 1;
    bool fits = (span <= 16);
    if (fits) for (int i = t; i < span * 128; i += 512) ((float*)spool)[i] = 0.f;
    __syncthreads();

    int d = t & 127;
    int q = t >> 7;   // 0..3
    float bg = 0.f, bb = 0.f, mu = 0.f, is = 0.f;
    if (!INIT) {
        bg = bng[d]; bb = bnb[d];
        float s = bnslot[d], sq = bnslot[128 + d];
        mu = s * (1.0f / NN);
        is = rsqrtf(sq * (1.0f / NN) - mu * mu + 1e-5f);
    }
    const float* sp = INIT ? src : d_rst;

    float racc = 0.f; int rlg = -1;
    for (int i = q; i < nodes; i += 4) {
        int n = base + i;
        float v = sp[n * 128 + d];
        float y;
        if (INIT) y = v;
        else      y = fmaxf((v - mu) * is * bg + bb, 0.0f);
        d_hsh[n * 128 + d] = __float2half_rn(y * d_norm_out[n]);
        int lg = gid[n] - g0;
        if (fits) {
            if (lg != rlg) {
                if (rlg >= 0) atomicAdd(&spool[rlg][d], racc);
                rlg = lg; racc = 0.f;
            }
            racc += y;
        } else {
            atomicAdd(&d_pooled[(pslot * NG + g0 + lg) * 128 + d], y);
        }
    }
    if (fits && rlg >= 0) atomicAdd(&spool[rlg][d], racc);
    __syncthreads();
    if (fits)
        for (int lg = q; lg < span; lg += 4)
            atomicAdd(&d_pooled[(pslot * NG + g0 + lg) * 128 + d], spool[lg][d]);
}

// fused: CSR fill (blocks [0,FILL_BLKS)) + init epilogue (blocks after)
__global__ __launch_bounds__(512) void fill_epi_kernel(const int* __restrict__ src,
                                                       const int* __restrict__ dst,
                                                       const float* __restrict__ feat,
                                                       const int* __restrict__ gid) {
    if (blockIdx.x < FILL_BLKS) {
        int i = blockIdx.x * 512 + threadIdx.x;
        if (i < NE) {
            int d = dst[i];
            int pos = atomicAdd(&d_cursor[d], 1);
            d_col[pos] = src[i];
        }
    } else {
        epilogue_body<true>(feat, gid, 0, nullptr, nullptr, nullptr,
                            blockIdx.x - FILL_BLKS);
    }
}

__global__ __launch_bounds__(512) void epilogue_kernel(const int* __restrict__ gid,
                                                       int pslot,
                                                       const float* __restrict__ bng,
                                                       const float* __restrict__ bnb,
                                                       const float* __restrict__ bnslot) {
    epilogue_body<false>(nullptr, gid, pslot, bng, bnb, bnslot, blockIdx.x);
}

// ---------------- SpMM: warp per dst node, lane-cooperative col fetch -------
__device__ __forceinline__ void acc_node(float4& acc, const __half* __restrict__ hs,
                                         int s, int lane) {
    uint2 u = *reinterpret_cast<const uint2*>(hs + s * 128 + lane * 4);
    float2 fa = __half22float2(*reinterpret_cast<__half2*>(&u.x));
    float2 fb = __half22float2(*reinterpret_cast<__half2*>(&u.y));
    acc.x += fa.x; acc.y += fa.y; acc.z += fb.x; acc.w += fb.y;
}

__global__ __launch_bounds__(256) void spmm_kernel() {
    int warp = (blockIdx.x * blockDim.x + threadIdx.x) >> 5;
    int lane = threadIdx.x & 31;
    if (warp >= NN) return;
    int beg = d_rowptr[warp], end = d_rowptr[warp + 1];
    float4 acc = make_float4(0.f, 0.f, 0.f, 0.f);
    const __half* hs = d_hsh;
    for (int e0 = beg; e0 < end; e0 += 32) {
        int m = min(32, end - e0);
        int c = (lane < m) ? __ldg(&d_col[e0 + lane]) : 0;
        int j = 0;
        for (; j + 4 <= m; j += 4) {
            int s0 = __shfl_sync(0xffffffffu, c, j);
            int s1 = __shfl_sync(0xffffffffu, c, j + 1);
            int s2 = __shfl_sync(0xffffffffu, c, j + 2);
            int s3 = __shfl_sync(0xffffffffu, c, j + 3);
            acc_node(acc, hs, s0, lane);
            acc_node(acc, hs, s1, lane);
            acc_node(acc, hs, s2, lane);
            acc_node(acc, hs, s3, lane);
        }
        for (; j < m; j++) {
            int s = __shfl_sync(0xffffffffu, c, j);
            acc_node(acc, hs, s, lane);
        }
    }
    float ni = 0.9f * d_norm_in[warp];
    float rs = 0.1f * d_sdeg[warp];
    float4 hv = make_float4(0.f, 0.f, 0.f, 0.f);
    acc_node(hv, hs, warp, lane);     // residual = hs[self] * sdeg
    float4 r;
    r.x = ni * acc.x + rs * hv.x;
    r.y = ni * acc.y + rs * hv.y;
    r.z = ni * acc.z + rs * hv.z;
    r.w = ni * acc.w + rs * hv.w;
    reinterpret_cast<float4*>(d_rst)[warp * 32 + lane] = r;
}

// ---------------- GEMM: rst = (1-B)*rst + B*(rst@W) + bias, in place -------
// BN partial sums now reduced via shfl-butterfly (no conflicting shared atomics)
__global__ __launch_bounds__(256) void gemm_kernel(const float* __restrict__ W,
                                                   const float* __restrict__ bias,
                                                   float* __restrict__ bnslot) {
    __shared__ __nv_bfloat16 As[128][72];
    __shared__ __nv_bfloat16 Ws[64][136];
    __shared__ float bns[8][256];   // per-warp private [sum(128) | sumsq(128)]
    int t = threadIdx.x, lane = t & 31, wid = t >> 5;
    int rowbase = blockIdx.x * 128;
    #pragma unroll
    for (int w = 0; w < 8; w++) ((float*)bns)[w * 256 + t] = 0.f;
    float acc[16][4];
    #pragma unroll
    for (int i = 0; i < 16; i++) { acc[i][0]=0.f; acc[i][1]=0.f; acc[i][2]=0.f; acc[i][3]=0.f; }

    for (int kk = 0; kk < 128; kk += 64) {
        for (int i = t; i < 128 * 16; i += 256) {
            int r = i >> 4, c4 = i & 15;
            int grow = rowbase + r;
            float4 v = make_float4(0.f, 0.f, 0.f, 0.f);
            if (grow < NN)
                v = reinterpret_cast<const float4*>(d_rst)[grow * 32 + (kk >> 2) + c4];
            __nv_bfloat162* ap = reinterpret_cast<__nv_bfloat162*>(&As[r][c4 * 4]);
            ap[0] = __floats2bfloat162_rn(v.x, v.y);
            ap[1] = __floats2bfloat162_rn(v.z, v.w);
        }
        for (int i = t; i < 64 * 32; i += 256) {
            int r = i >> 5, c4 = i & 31;
            float4 v = reinterpret_cast<const float4*>(W)[(kk + r) * 32 + c4];
            __nv_bfloat162* wp = reinterpret_cast<__nv_bfloat162*>(&Ws[r][c4 * 4]);
            wp[0] = __floats2bfloat162_rn(v.x, v.y);
            wp[1] = __floats2bfloat162_rn(v.z, v.w);
        }
        __syncthreads();

        #pragma unroll
        for (int k0 = 0; k0 < 64; k0 += 16) {
            uint32_t a[4];
            unsigned aaddr = (unsigned)__cvta_generic_to_shared(
                &As[wid * 16 + (lane & 15)][k0 + ((lane >> 1) & 8)]);
            asm volatile("ldmatrix.sync.aligned.m8n8.x4.shared.b16 {%0,%1,%2,%3}, [%4];"
                         : "=r"(a[0]), "=r"(a[1]), "=r"(a[2]), "=r"(a[3]) : "r"(aaddr));
            unsigned bbase = (unsigned)__cvta_generic_to_shared(&Ws[k0 + (lane & 15)][0]);
            #pragma unroll
            for (int nb = 0; nb < 16; nb++) {
                uint32_t b[2];
                asm volatile("ldmatrix.sync.aligned.m8n8.x2.trans.shared.b16 {%0,%1}, [%2];"
                             : "=r"(b[0]), "=r"(b[1]) : "r"(bbase + nb * 16));
                asm volatile("mma.sync.aligned.m16n8k16.row.col.f32.bf16.bf16.f32 "
                             "{%0,%1,%2,%3},{%4,%5,%6,%7},{%8,%9},{%0,%1,%2,%3};"
                             : "+f"(acc[nb][0]), "+f"(acc[nb][1]), "+f"(acc[nb][2]), "+f"(acc[nb][3])
                             : "r"(a[0]), "r"(a[1]), "r"(a[2]), "r"(a[3]), "r"(b[0]), "r"(b[1]));
            }
        }
        __syncthreads();
    }
    int r0 = rowbase + wid * 16 + (lane >> 2);
    int r1 = r0 + 8;
    #pragma unroll
    for (int nb = 0; nb < 16; nb++) {
        int c = nb * 8 + (lane & 3) * 2;
        float b0 = bias[c], b1 = bias[c + 1];
        float s0 = 0.f, s1 = 0.f, q0 = 0.f, q1 = 0.f;
        if (r0 < NN) {
            float* p = &d_rst[r0 * 128 + c];
            float y0 = OMBF * p[0] + BETAF * acc[nb][0] + b0;
            float y1 = OMBF * p[1] + BETAF * acc[nb][1] + b1;
            p[0] = y0; p[1] = y1;
            s0 += y0; s1 += y1; q0 += y0 * y0; q1 += y1 * y1;
        }
        if (r1 < NN) {
            float* p = &d_rst[r1 * 128 + c];
            float y0 = OMBF * p[0] + BETAF * acc[nb][2] + b0;
            float y1 = OMBF * p[1] + BETAF * acc[nb][3] + b1;
            p[0] = y0; p[1] = y1;
            s0 += y0; s1 += y1; q0 += y0 * y0; q1 += y1 * y1;
        }
        // butterfly over the 8 lanes (lane>>2 = 0..7) sharing column c
        #pragma unroll
        for (int m = 4; m <= 16; m <<= 1) {
            s0 += __shfl_xor_sync(0xffffffffu, s0, m);
            s1 += __shfl_xor_sync(0xffffffffu, s1, m);
            q0 += __shfl_xor_sync(0xffffffffu, q0, m);
            q1 += __shfl_xor_sync(0xffffffffu, q1, m);
        }
        if (lane < 4) {   // lanes 0..3 hold totals for their (c, c+1)
            bns[wid][c]           += s0;
            bns[wid][c + 1]       += s1;
            bns[wid][128 + c]     += q0;
            bns[wid][128 + c + 1] += q1;
        }
    }
    __syncthreads();
    float v = 0.f;
    #pragma unroll
    for (int w = 0; w < 8; w++) v += bns[w][t & 255];
    atomicAdd(&bnslot[t], v);
}

// ---------------- readout ----------------
__global__ void final_kernel(const float* __restrict__ lin_w,
                             const float* __restrict__ lin_b,
                             float* __restrict__ out) {
    __shared__ float sp[6][128];
    __shared__ float sc[NOUT];
    int g = blockIdx.x, t = threadIdx.x;   // 128 threads
    for (int i = t; i < 6 * 128; i += 128)
        sp[i / 128][i & 127] = d_pooled[((i / 128) * NG + g) * 128 + (i & 127)];
    __syncthreads();
    if (t < NOUT) {
        float s = 0.f;
        for (int i = 0; i < 6; i++) {
            s += lin_b[i * NOUT + t];
            const float* w = lin_w + i * 128 * NOUT;
            float ps = 0.f;
            for (int k = 0; k < 128; k++) ps += sp[i][k] * w[k * NOUT + t];
            s += ps;
        }
        sc[t] = s;
    }
    __syncthreads();
    if (t < NOUT) {
        float m = sc[0];
        #pragma unroll
        for (int i = 1; i < NOUT; i++) m = fmaxf(m, sc[i]);
        float lse = 0.f;
        #pragma unroll
        for (int i = 0; i < NOUT; i++) lse += expf(sc[i] - m);
        lse = logf(lse);
        out[g * NOUT + t] = sc[t] - m - lse;
    }
    float mp = sp[1][t] + sp[2][t] + sp[3][t] + sp[4][t] + sp[5][t];
    out[NG * NOUT + g * 128 + t] = mp * 0.2f;
}

// ---------------- trailing cleanup: restore zero state for next replay -----
__global__ void cleanup_kernel() {
    int i = blockIdx.x * blockDim.x + threadIdx.x;
    if (i < NN) { d_deg_out[i] = 0; d_deg_in[i] = 0; }
    if (i < (NLAY+1)*NG*DD) d_pooled[i] = 0.f;
    if (i < NLAY*2*DD) d_bnsum[i] = 0.f;
    if (i < NBLK) d_pub[i] = 0;
}

// ---------------- host launcher ----------------
extern "C" void kernel_launch(void* const* d_in, const int* in_sizes, int n_in,
                              void* d_out, int out_size) {
    const float* feat  = (const float*)d_in[0];
    const int*   src   = (const int*)  d_in[1];
    const int*   dst   = (const int*)  d_in[2];
    const int*   gid   = (const int*)  d_in[3];
    const float* gcn_w = (const float*)d_in[4];
    const float* gcn_b = (const float*)d_in[5];
    const float* bn_g  = (const float*)d_in[6];
    const float* bn_b  = (const float*)d_in[7];
    const float* lin_w = (const float*)d_in[8];
    const float* lin_b = (const float*)d_in[9];
    float* out = (float*)d_out;
    (void)in_sizes; (void)n_in; (void)out_size;

    float* bnsum_base;
    cudaGetSymbolAddress((void**)&bnsum_base, d_bnsum);

    deg_kernel<<<(NE + 255) / 256, 256>>>(src, dst);
    scan_fused<<<NBLK, 256>>>();
    fill_epi_kernel<<<FILL_BLKS + EPI_BLKS, 512>>>(src, dst, feat, gid);

    for (int l = 0; l < NLAY; l++) {
        spmm_kernel<<<(NN * 32 + 255) / 256, 256>>>();        // first spmm = idx 3
        gemm_kernel<<<(NN + 127) / 128, 256>>>(gcn_w + l * DD * DD, gcn_b + l * DD,
                                               bnsum_base + l * 2 * DD);
        epilogue_kernel<<<EPI_BLKS, 512>>>(gid, l + 1,
                                           bn_g + l * DD, bn_b + l * DD,
                                           bnsum_base + l * 2 * DD);
    }
    final_kernel<<<NG, 128>>>(lin_w, lin_b, out);
    cleanup_kernel<<<600, 256>>>();
}

// round 7
// speedup vs baseline: 1.8736x; 1.1099x over previous
#include <cuda_runtime.h>
#include <cuda_fp16.h>
#include <cuda_bf16.h>
#include <cstdint>

#define NN   100000
#define NE   600000
#define DD   128
#define NG   200
#define NLAY 5
#define NOUT 10
#define NBLK 98                 // ceil(NN/1024)
#define FILL_BLKS 1172          // ceil(NE/512)
#define EPI_BLKS  391           // ceil(NN/256)
#define BETAF 0.0077821404f     // ln(1 + 1/128)
#define OMBF  0.9922178596f     // 1 - BETA

// ---------------- scratch (device globals; no allocations) ----------------
// All accumulator-style globals start zero (static init) and are re-zeroed by
// cleanup_kernel at the END of every launch, so each graph replay starts clean.
__device__ __align__(16) __half d_hsh[NN*DD];  // fp16: h * norm_out (gather table)
__device__ __align__(16) float  d_rst[NN*DD];
__device__ float d_norm_out[NN];
__device__ float d_sdeg[NN];
__device__ float d_norm_in [NN];
__device__ int   d_deg_out[NN];
__device__ int   d_deg_in [NN];
__device__ int   d_rowptr[NN+1];
__device__ int   d_cursor[NN];
__device__ int   d_col[NE];
__device__ float d_pooled[(NLAY+1)*NG*DD];
__device__ float d_bnsum[NLAY*2*DD];
__device__ int   d_pub[NBLK];                  // decoupled-lookback publish words

// ---------------- degree histogram ----------------
__global__ void deg_kernel(const int* __restrict__ src, const int* __restrict__ dst) {
    int i = blockIdx.x * blockDim.x + threadIdx.x;
    if (i < NE) {
        atomicAdd(&d_deg_out[src[i]], 1);
        atomicAdd(&d_deg_in [dst[i]], 1);
    }
}

// ---------------- fused norms + single-pass exclusive scan (lookback) -------
__global__ __launch_bounds__(256) void scan_fused() {
    __shared__ int sh[256];
    __shared__ int spre[128];
    int t = threadIdx.x, b = blockIdx.x, base = b * 1024;

    int loc[4]; int s = 0;
    #pragma unroll
    for (int i = 0; i < 4; i++) {
        int idx = base + t * 4 + i;
        int v = 0;
        if (idx < NN) {
            int dgo = max(d_deg_out[idx], 1);
            d_norm_out[idx] = rsqrtf((float)dgo);
            d_sdeg[idx]     = sqrtf((float)dgo);
            v = d_deg_in[idx];
            d_norm_in[idx]  = rsqrtf((float)max(v, 1));
        }
        loc[i] = s; s += v;
    }
    sh[t] = s; __syncthreads();
    for (int off = 1; off < 256; off <<= 1) {
        int v = (t >= off) ? sh[t - off] : 0;
        __syncthreads();
        sh[t] += v;
        __syncthreads();
    }
    // publish this block's aggregate (value+1; 0 == not ready)
    if (t == 0) atomicExch(&d_pub[b], sh[255] + 1);

    // lookback: lane t spins on predecessor t (all 98 blocks co-resident)
    int myagg = 0;
    if (t < b) {
        volatile int* p = &d_pub[t];
        int v;
        do { v = *p; } while (v == 0);
        myagg = v - 1;
    }
    if (t < 128) spre[t] = myagg;
    __syncthreads();
    for (int off = 64; off > 0; off >>= 1) {
        if (t < off) spre[t] += spre[t + off];
        __syncthreads();
    }
    int bpre = spre[0];

    int tpre = (t == 0) ? 0 : sh[t - 1];
    #pragma unroll
    for (int i = 0; i < 4; i++) {
        int idx = base + t * 4 + i;
        if (idx < NN) { int p = bpre + tpre + loc[i]; d_rowptr[idx] = p; d_cursor[idx] = p; }
    }
    if (b == 0 && t == 0) d_rowptr[NN] = NE;
}

// ---------------- BN+ReLU epilogue body ----------------
template <bool INIT>
__device__ __forceinline__ void epilogue_body(const float* __restrict__ src,
                                              const int* __restrict__ gid,
                                              int pslot,
                                              const float* __restrict__ bng,
                                              const float* __restrict__ bnb,
                                              const float* __restrict__ bnslot,
                                              int blk) {
    __shared__ float spool[16][128];
    int t = threadIdx.x;
    int base = blk * 256;
    int nodes = min(256, NN - base);
    if (nodes <= 0) return;
    int g0 = gid[base];
    int span = gid[base + nodes - 1] - g0 + 1;
    bool fits = (span <= 16);
    if (fits) for (int i = t; i < span * 128; i += 512) ((float*)spool)[i] = 0.f;
    __syncthreads();

    int d = t & 127;
    int q = t >> 7;   // 0..3
    float bg = 0.f, bb = 0.f, mu = 0.f, is = 0.f;
    if (!INIT) {
        bg = bng[d]; bb = bnb[d];
        float s = bnslot[d], sq = bnslot[128 + d];
        mu = s * (1.0f / NN);
        is = rsqrtf(sq * (1.0f / NN) - mu * mu + 1e-5f);
    }
    const float* sp = INIT ? src : d_rst;

    float racc = 0.f; int rlg = -1;
    for (int i = q; i < nodes; i += 4) {
        int n = base + i;
        float v = sp[n * 128 + d];
        float y;
        if (INIT) y = v;
        else      y = fmaxf((v - mu) * is * bg + bb, 0.0f);
        d_hsh[n * 128 + d] = __float2half_rn(y * d_norm_out[n]);
        int lg = gid[n] - g0;
        if (fits) {
            if (lg != rlg) {
                if (rlg >= 0) atomicAdd(&spool[rlg][d], racc);
                rlg = lg; racc = 0.f;
            }
            racc += y;
        } else {
            atomicAdd(&d_pooled[(pslot * NG + g0 + lg) * 128 + d], y);
        }
    }
    if (fits && rlg >= 0) atomicAdd(&spool[rlg][d], racc);
    __syncthreads();
    if (fits)
        for (int lg = q; lg < span; lg += 4)
            atomicAdd(&d_pooled[(pslot * NG + g0 + lg) * 128 + d], spool[lg][d]);
}

// fused: CSR fill (blocks [0,FILL_BLKS)) + init epilogue (blocks after)
__global__ __launch_bounds__(512) void fill_epi_kernel(const int* __restrict__ src,
                                                       const int* __restrict__ dst,
                                                       const float* __restrict__ feat,
                                                       const int* __restrict__ gid) {
    if (blockIdx.x < FILL_BLKS) {
        int i = blockIdx.x * 512 + threadIdx.x;
        if (i < NE) {
            int d = dst[i];
            int pos = atomicAdd(&d_cursor[d], 1);
            d_col[pos] = src[i];
        }
    } else {
        epilogue_body<true>(feat, gid, 0, nullptr, nullptr, nullptr,
                            blockIdx.x - FILL_BLKS);
    }
}

__global__ __launch_bounds__(512) void epilogue_kernel(const int* __restrict__ gid,
                                                       int pslot,
                                                       const float* __restrict__ bng,
                                                       const float* __restrict__ bnb,
                                                       const float* __restrict__ bnslot) {
    epilogue_body<false>(nullptr, gid, pslot, bng, bnb, bnslot, blockIdx.x);
}

// ---------------- SpMM: warp per dst node, lane-cooperative col fetch -------
__device__ __forceinline__ void acc_node(float4& acc, const __half* __restrict__ hs,
                                         int s, int lane) {
    uint2 u = *reinterpret_cast<const uint2*>(hs + s * 128 + lane * 4);
    float2 fa = __half22float2(*reinterpret_cast<__half2*>(&u.x));
    float2 fb = __half22float2(*reinterpret_cast<__half2*>(&u.y));
    acc.x += fa.x; acc.y += fa.y; acc.z += fb.x; acc.w += fb.y;
}

__global__ __launch_bounds__(256) void spmm_kernel() {
    int warp = (blockIdx.x * blockDim.x + threadIdx.x) >> 5;
    int lane = threadIdx.x & 31;
    if (warp >= NN) return;
    int beg = d_rowptr[warp], end = d_rowptr[warp + 1];
    float4 acc = make_float4(0.f, 0.f, 0.f, 0.f);
    const __half* hs = d_hsh;
    for (int e0 = beg; e0 < end; e0 += 32) {
        int m = min(32, end - e0);
        int c = (lane < m) ? __ldg(&d_col[e0 + lane]) : 0;
        int j = 0;
        for (; j + 4 <= m; j += 4) {
            int s0 = __shfl_sync(0xffffffffu, c, j);
            int s1 = __shfl_sync(0xffffffffu, c, j + 1);
            int s2 = __shfl_sync(0xffffffffu, c, j + 2);
            int s3 = __shfl_sync(0xffffffffu, c, j + 3);
            acc_node(acc, hs, s0, lane);
            acc_node(acc, hs, s1, lane);
            acc_node(acc, hs, s2, lane);
            acc_node(acc, hs, s3, lane);
        }
        for (; j < m; j++) {
            int s = __shfl_sync(0xffffffffu, c, j);
            acc_node(acc, hs, s, lane);
        }
    }
    float ni = 0.9f * d_norm_in[warp];
    float rs = 0.1f * d_sdeg[warp];
    float4 hv = make_float4(0.f, 0.f, 0.f, 0.f);
    acc_node(hv, hs, warp, lane);     // residual = hs[self] * sdeg
    float4 r;
    r.x = ni * acc.x + rs * hv.x;
    r.y = ni * acc.y + rs * hv.y;
    r.z = ni * acc.z + rs * hv.z;
    r.w = ni * acc.w + rs * hv.w;
    reinterpret_cast<float4*>(d_rst)[warp * 32 + lane] = r;
}

// ---------------- GEMM: rst = (1-B)*rst + B*(rst@W) + bias, in place -------
// Epilogue stages acc through smem (two 64-row passes) so the rst RMW is
// fully coalesced float4 row traffic; BN partials accumulate in registers
// (fixed 4 columns per thread) -> conflict-free per-warp smem, no shuffles.
__global__ __launch_bounds__(256) void gemm_kernel(const float* __restrict__ W,
                                                   const float* __restrict__ bias,
                                                   float* __restrict__ bnslot) {
    __shared__ __align__(16) char usm[35840];   // union: (As+Ws) | Os
    __nv_bfloat16 (*As)[72]  = reinterpret_cast<__nv_bfloat16(*)[72]>(usm);          // 18432B
    __nv_bfloat16 (*Ws)[136] = reinterpret_cast<__nv_bfloat16(*)[136]>(usm + 18432); // 17408B
    float (*Os)[132]         = reinterpret_cast<float(*)[132]>(usm);                 // 33792B
    __shared__ float bns[8][256];   // per-warp [sum(128) | sumsq(128)]
    int t = threadIdx.x, lane = t & 31, wid = t >> 5;
    int rowbase = blockIdx.x * 128;
    float acc[16][4];
    #pragma unroll
    for (int i = 0; i < 16; i++) { acc[i][0]=0.f; acc[i][1]=0.f; acc[i][2]=0.f; acc[i][3]=0.f; }

    for (int kk = 0; kk < 128; kk += 64) {
        for (int i = t; i < 128 * 16; i += 256) {
            int r = i >> 4, c4 = i & 15;
            int grow = rowbase + r;
            float4 v = make_float4(0.f, 0.f, 0.f, 0.f);
            if (grow < NN)
                v = reinterpret_cast<const float4*>(d_rst)[grow * 32 + (kk >> 2) + c4];
            __nv_bfloat162* ap = reinterpret_cast<__nv_bfloat162*>(&As[r][c4 * 4]);
            ap[0] = __floats2bfloat162_rn(v.x, v.y);
            ap[1] = __floats2bfloat162_rn(v.z, v.w);
        }
        for (int i = t; i < 64 * 32; i += 256) {
            int r = i >> 5, c4 = i & 31;
            float4 v = reinterpret_cast<const float4*>(W)[(kk + r) * 32 + c4];
            __nv_bfloat162* wp = reinterpret_cast<__nv_bfloat162*>(&Ws[r][c4 * 4]);
            wp[0] = __floats2bfloat162_rn(v.x, v.y);
            wp[1] = __floats2bfloat162_rn(v.z, v.w);
        }
        __syncthreads();

        #pragma unroll
        for (int k0 = 0; k0 < 64; k0 += 16) {
            uint32_t a[4];
            unsigned aaddr = (unsigned)__cvta_generic_to_shared(
                &As[wid * 16 + (lane & 15)][k0 + ((lane >> 1) & 8)]);
            asm volatile("ldmatrix.sync.aligned.m8n8.x4.shared.b16 {%0,%1,%2,%3}, [%4];"
                         : "=r"(a[0]), "=r"(a[1]), "=r"(a[2]), "=r"(a[3]) : "r"(aaddr));
            unsigned bbase = (unsigned)__cvta_generic_to_shared(&Ws[k0 + (lane & 15)][0]);
            #pragma unroll
            for (int nb = 0; nb < 16; nb++) {
                uint32_t b[2];
                asm volatile("ldmatrix.sync.aligned.m8n8.x2.trans.shared.b16 {%0,%1}, [%2];"
                             : "=r"(b[0]), "=r"(b[1]) : "r"(bbase + nb * 16));
                asm volatile("mma.sync.aligned.m16n8k16.row.col.f32.bf16.bf16.f32 "
                             "{%0,%1,%2,%3},{%4,%5,%6,%7},{%8,%9},{%0,%1,%2,%3};"
                             : "+f"(acc[nb][0]), "+f"(acc[nb][1]), "+f"(acc[nb][2]), "+f"(acc[nb][3])
                             : "r"(a[0]), "r"(a[1]), "r"(a[2]), "r"(a[3]), "r"(b[0]), "r"(b[1]));
            }
        }
        __syncthreads();
    }

    // ---- staged epilogue: two 64-row passes through Os ----
    int c4 = t & 31;                       // thread's fixed float4 column group
    float4 bias4 = reinterpret_cast<const float4*>(bias)[c4];
    float sA[4] = {0.f, 0.f, 0.f, 0.f};
    float qA[4] = {0.f, 0.f, 0.f, 0.f};
    #pragma unroll
    for (int p = 0; p < 2; p++) {
        if ((wid >> 2) == p) {             // warps owning rows [p*64, p*64+64)
            int r0 = (wid & 3) * 16 + (lane >> 2);
            #pragma unroll
            for (int nb = 0; nb < 16; nb++) {
                int c = nb * 8 + (lane & 3) * 2;
                *reinterpret_cast<float2*>(&Os[r0][c])     = make_float2(acc[nb][0], acc[nb][1]);
                *reinterpret_cast<float2*>(&Os[r0 + 8][c]) = make_float2(acc[nb][2], acc[nb][3]);
            }
        }
        __syncthreads();
        #pragma unroll
        for (int it = 0; it < 8; it++) {
            int r = it * 8 + wid;          // 0..63 within pass
            int grow = rowbase + p * 64 + r;
            if (grow < NN) {
                float4 rv = reinterpret_cast<const float4*>(d_rst)[grow * 32 + c4];
                float4 av = *reinterpret_cast<const float4*>(&Os[r][c4 * 4]);
                float4 y;
                y.x = OMBF * rv.x + BETAF * av.x + bias4.x;
                y.y = OMBF * rv.y + BETAF * av.y + bias4.y;
                y.z = OMBF * rv.z + BETAF * av.z + bias4.z;
                y.w = OMBF * rv.w + BETAF * av.w + bias4.w;
                reinterpret_cast<float4*>(d_rst)[grow * 32 + c4] = y;
                sA[0] += y.x; qA[0] += y.x * y.x;
                sA[1] += y.y; qA[1] += y.y * y.y;
                sA[2] += y.z; qA[2] += y.z * y.z;
                sA[3] += y.w; qA[3] += y.w * y.w;
            }
        }
        __syncthreads();
    }
    #pragma unroll
    for (int j = 0; j < 4; j++) {
        bns[wid][c4 * 4 + j]       = sA[j];
        bns[wid][128 + c4 * 4 + j] = qA[j];
    }
    __syncthreads();
    float v = 0.f;
    #pragma unroll
    for (int w = 0; w < 8; w++) v += bns[w][t];
    atomicAdd(&bnslot[t], v);
}

// ---------------- readout ----------------
__global__ void final_kernel(const float* __restrict__ lin_w,
                             const float* __restrict__ lin_b,
                             float* __restrict__ out) {
    __shared__ float sp[6][128];
    __shared__ float sc[NOUT];
    int g = blockIdx.x, t = threadIdx.x;   // 128 threads
    for (int i = t; i < 6 * 128; i += 128)
        sp[i / 128][i & 127] = d_pooled[((i / 128) * NG + g) * 128 + (i & 127)];
    __syncthreads();
    if (t < NOUT) {
        float s = 0.f;
        for (int i = 0; i < 6; i++) {
            s += lin_b[i * NOUT + t];
            const float* w = lin_w + i * 128 * NOUT;
            float ps = 0.f;
            for (int k = 0; k < 128; k++) ps += sp[i][k] * w[k * NOUT + t];
            s += ps;
        }
        sc[t] = s;
    }
    __syncthreads();
    if (t < NOUT) {
        float m = sc[0];
        #pragma unroll
        for (int i = 1; i < NOUT; i++) m = fmaxf(m, sc[i]);
        float lse = 0.f;
        #pragma unroll
        for (int i = 0; i < NOUT; i++) lse += expf(sc[i] - m);
        lse = logf(lse);
        out[g * NOUT + t] = sc[t] - m - lse;
    }
    float mp = sp[1][t] + sp[2][t] + sp[3][t] + sp[4][t] + sp[5][t];
    out[NG * NOUT + g * 128 + t] = mp * 0.2f;
}

// ---------------- trailing cleanup: restore zero state for next replay -----
__global__ void cleanup_kernel() {
    int i = blockIdx.x * blockDim.x + threadIdx.x;
    if (i < NN) { d_deg_out[i] = 0; d_deg_in[i] = 0; }
    if (i < (NLAY+1)*NG*DD) d_pooled[i] = 0.f;
    if (i < NLAY*2*DD) d_bnsum[i] = 0.f;
    if (i < NBLK) d_pub[i] = 0;
}

// ---------------- host launcher ----------------
extern "C" void kernel_launch(void* const* d_in, const int* in_sizes, int n_in,
                              void* d_out, int out_size) {
    const float* feat  = (const float*)d_in[0];
    const int*   src   = (const int*)  d_in[1];
    const int*   dst   = (const int*)  d_in[2];
    const int*   gid   = (const int*)  d_in[3];
    const float* gcn_w = (const float*)d_in[4];
    const float* gcn_b = (const float*)d_in[5];
    const float* bn_g  = (const float*)d_in[6];
    const float* bn_b  = (const float*)d_in[7];
    const float* lin_w = (const float*)d_in[8];
    const float* lin_b = (const float*)d_in[9];
    float* out = (float*)d_out;
    (void)in_sizes; (void)n_in; (void)out_size;

    float* bnsum_base;
    cudaGetSymbolAddress((void**)&bnsum_base, d_bnsum);

    deg_kernel<<<(NE + 255) / 256, 256>>>(src, dst);
    scan_fused<<<NBLK, 256>>>();
    fill_epi_kernel<<<FILL_BLKS + EPI_BLKS, 512>>>(src, dst, feat, gid);

    for (int l = 0; l < NLAY; l++) {
        spmm_kernel<<<(NN * 32 + 255) / 256, 256>>>();        // first spmm = idx 3
        gemm_kernel<<<(NN + 127) / 128, 256>>>(gcn_w + l * DD * DD, gcn_b + l * DD,
                                               bnsum_base + l * 2 * DD);
        epilogue_kernel<<<EPI_BLKS, 512>>>(gid, l + 1,
                                           bn_g + l * DD, bn_b + l * DD,
                                           bnsum_base + l * 2 * DD);
    }
    final_kernel<<<NG, 128>>>(lin_w, lin_b, out);
    cleanup_kernel<<<600, 256>>>();
}